// round 14
// baseline (speedup 1.0000x reference)
#include <cuda_runtime.h>
#include <cuda_fp16.h>
#include <stdint.h>

// ---------------------------------------------------------------------------
// TCNN INR fused: hash-grid encoding + MLP 48->128->128->1, fp16 HMMA path.
// WARP-SPECIALIZED: per 192-thread CTA, warps 0-3 = GEMM consumers (M=64,
// 4 N-groups of 32 cols, weights persistent in registers), warps 4-5 = encode
// producers (32 pixels each; warp-uniform level gathers, 4 chunks x 3 levels).
// Persistent grid (304 CTAs = 2/SM); double-buffered X; named barriers:
//   bar 1 (192 thr) = batch handshake, bar 2 (128 thr) = consumer-internal.
// Encodings scaled by 2^14 to dodge fp16 subnormals (undone in epilogue).
// ---------------------------------------------------------------------------

#define NBATCH 16384           // 1024*1024 / 64 pixels per batch
#define NCTA 304               // 2 per SM, grid-stride over batches
#define NTHREADS 192
#define SCALE 16384.0f
#define INV_SCALE (1.0f / 16384.0f)

#define XS_STRIDE_H 56         // 48 cols + pad (112B rows, 16B-aligned)
#define H1_STRIDE_H 136        // 128 cols + pad (272B rows, 16B-aligned)
#define SM_X_BYTES (64 * XS_STRIDE_H * 2)     // 7168 (x2 buffers)
#define SM_H1_BYTES (64 * H1_STRIDE_H * 2)    // 17408
#define SM_PART_BYTES (4 * 64 * 4)            // 1024
#define SMEM_BYTES (2 * SM_X_BYTES + SM_H1_BYTES + SM_PART_BYTES)

#define BAR_ALL()  asm volatile("bar.sync 1, %0;" :: "n"(NTHREADS) : "memory")
#define BAR_CONS() asm volatile("bar.sync 2, 128;" ::: "memory")

__constant__ float c_scale[12] = {
    15.0f, 23.0f, 35.0f, 53.0f, 80.0f, 120.5f, 181.25f, 272.375f,
    409.0625f, 614.09375f, 921.640625f, 1382.9609375f};
__constant__ uint32_t c_res[12] = {16, 24, 36, 54, 81, 122, 183, 274, 411, 616, 923, 1384};

static __device__ __forceinline__ uint32_t packh2(float lo, float hi) {
    __half2 h = __floats2half2_rn(lo, hi);
    return *(uint32_t*)&h;
}

static __device__ __forceinline__ void mma16(float d[4], const uint32_t a[4], const uint32_t b[2]) {
    asm volatile(
        "mma.sync.aligned.m16n8k16.row.col.f32.f16.f16.f32 "
        "{%0,%1,%2,%3}, {%4,%5,%6,%7}, {%8,%9}, {%0,%1,%2,%3};"
        : "+f"(d[0]), "+f"(d[1]), "+f"(d[2]), "+f"(d[3])
        : "r"(a[0]), "r"(a[1]), "r"(a[2]), "r"(a[3]), "r"(b[0]), "r"(b[1]));
}

#define LDSM_X4(r, addr) \
    asm volatile("ldmatrix.sync.aligned.m8n8.x4.shared.b16 {%0,%1,%2,%3}, [%4];" \
        : "=r"((r)[0]), "=r"((r)[1]), "=r"((r)[2]), "=r"((r)[3]) : "r"(addr))

#define STSM_X4(addr, r0, r1, r2, r3) \
    asm volatile("stmatrix.sync.aligned.m8n8.x4.shared.b16 [%0], {%1,%2,%3,%4};" \
        :: "r"(addr), "r"(r0), "r"(r1), "r"(r2), "r"(r3) : "memory")

// 3-level encoding chunk (producer-only; producers have register headroom)
struct EncChunk3 {
    float4 t[3][4];
    float wx[3], wy[3];
};

static __device__ __forceinline__ void enc_gather3(
    int lb, float fx, float fy, const float4* __restrict__ tab, EncChunk3& c)
{
#pragma unroll
    for (int j = 0; j < 3; j++) {
        const int l = lb + j;
        const float s = c_scale[l];
        const uint32_t R = c_res[l];
        float px = fx * s + 0.5f, py = fy * s + 0.5f;
        float fpx = floorf(px), fpy = floorf(py);
        c.wx[j] = px - fpx; c.wy[j] = py - fpy;
        uint32_t ux = (uint32_t)fpx, uy = (uint32_t)fpy;
        uint32_t x0 = min(ux, R - 1u), x1 = min(ux + 1u, R - 1u);
        uint32_t y0 = min(uy, R - 1u), y1 = min(uy + 1u, R - 1u);
        uint32_t i00, i10, i01, i11;
        if (l < 11) {
            i00 = x0 + y0 * R; i10 = x1 + y0 * R;
            i01 = x0 + y1 * R; i11 = x1 + y1 * R;
        } else {
            uint32_t h0 = y0 * 2654435761u, h1 = y1 * 2654435761u;
            i00 = (x0 ^ h0) & 0xFFFFFu; i10 = (x1 ^ h0) & 0xFFFFFu;
            i01 = (x0 ^ h1) & 0xFFFFFu; i11 = (x1 ^ h1) & 0xFFFFFu;
        }
        const float4* base = tab + ((size_t)l << 20);
        c.t[j][0] = __ldg(base + i00);
        c.t[j][1] = __ldg(base + i10);
        c.t[j][2] = __ldg(base + i01);
        c.t[j][3] = __ldg(base + i11);
    }
}

static __device__ __forceinline__ void enc_store3(int lb, const EncChunk3& c, uint2* dst)
{
#pragma unroll
    for (int j = 0; j < 3; j++) {
        float wx = c.wx[j], wy = c.wy[j];
        float w00 = (1.f - wx) * (1.f - wy) * SCALE, w10 = wx * (1.f - wy) * SCALE;
        float w01 = (1.f - wx) * wy * SCALE,         w11 = wx * wy * SCALE;
        float e0 = c.t[j][0].x * w00 + c.t[j][1].x * w10 + c.t[j][2].x * w01 + c.t[j][3].x * w11;
        float e1 = c.t[j][0].y * w00 + c.t[j][1].y * w10 + c.t[j][2].y * w01 + c.t[j][3].y * w11;
        float e2 = c.t[j][0].z * w00 + c.t[j][1].z * w10 + c.t[j][2].z * w01 + c.t[j][3].z * w11;
        float e3 = c.t[j][0].w * w00 + c.t[j][1].w * w10 + c.t[j][2].w * w01 + c.t[j][3].w * w11;
        uint2 v;
        v.x = packh2(e0, e1);
        v.y = packh2(e2, e3);
        dst[lb + j] = v;
    }
}

// producer: encode 32 pixels (one per lane) x 12 levels
static __device__ __forceinline__ void encode_batch32(
    int b, int r, const float4* __restrict__ tab, __half* Xn)
{
    const int pix = b * 64 + r;
    const float fx = (float)(pix & 1023) * (1.0f / 1023.0f);
    const float fy = (float)(pix >> 10) * (1.0f / 1023.0f);
    uint2* dst = (uint2*)(Xn + r * XS_STRIDE_H);
    EncChunk3 c;
#pragma unroll
    for (int k = 0; k < 4; k++) {
        enc_gather3(3 * k, fx, fy, tab, c);
        enc_store3(3 * k, c, dst);
    }
}

__global__ __launch_bounds__(NTHREADS, 2) void inr_kernel(
    const float4* __restrict__ tab,   // [12][2^20] float4
    const float* __restrict__ w1,     // [48][128]
    const float* __restrict__ w2,     // [128][128]
    const float* __restrict__ w3,     // [128]
    float* __restrict__ out)          // [1024*1024]
{
    extern __shared__ char smem[];
    __half* X0 = (__half*)smem;                        // [64][56] buffer 0
    __half* X1 = (__half*)(smem + SM_X_BYTES);         // [64][56] buffer 1
    __half* H1h = (__half*)(smem + 2 * SM_X_BYTES);    // [64][136]
    float* part = (float*)(smem + 2 * SM_X_BYTES + SM_H1_BYTES);

    const int tid = threadIdx.x;
    const int lane = tid & 31;

    if (tid >= 128) {
        // ================ PRODUCER WARPS (encoding, 2 warps) ================
        const int r = ((tid >> 5) - 4) * 32 + lane;    // pixel row 0..63
        encode_batch32(blockIdx.x, r, tab, X0);        // prologue -> X0
        BAR_ALL();
        int p = 0;
        for (int b = blockIdx.x; b < NBATCH; b += NCTA) {
            // encode NEXT batch into the other buffer (clamped coords on tail)
            encode_batch32(b + NCTA, r, tab, p ? X0 : X1);
            BAR_ALL();
            p ^= 1;
        }
        return;
    }

    // ======================= CONSUMER WARPS (GEMMs) =========================
    const int ng = tid >> 5;            // warp = N-group (32 cols)
    const int q = lane & 3, ln4 = lane >> 2;
    const int lrow = lane & 15;
    const int lcol = (lane >> 4) << 3;

    const uint32_t Xu0 = (uint32_t)__cvta_generic_to_shared(X0);
    const uint32_t Xu1 = (uint32_t)__cvta_generic_to_shared(X1);
    const uint32_t H1u = (uint32_t)__cvta_generic_to_shared(H1h);

    // ---- persistent B fragments (weights), loaded once per CTA ----
    uint32_t B1[3][4][2];
    uint32_t B2[8][4][2];
#pragma unroll
    for (int s = 0; s < 3; s++)
#pragma unroll
        for (int nt = 0; nt < 4; nt++) {
            int kb = s * 16 + 2 * q;
            int n = ng * 32 + nt * 8 + ln4;
            B1[s][nt][0] = packh2(w1[(kb + 0) * 128 + n], w1[(kb + 1) * 128 + n]);
            B1[s][nt][1] = packh2(w1[(kb + 8) * 128 + n], w1[(kb + 9) * 128 + n]);
        }
#pragma unroll
    for (int s = 0; s < 8; s++)
#pragma unroll
        for (int nt = 0; nt < 4; nt++) {
            int kb = s * 16 + 2 * q;
            int n = ng * 32 + nt * 8 + ln4;
            B2[s][nt][0] = packh2(w2[(kb + 0) * 128 + n], w2[(kb + 1) * 128 + n]);
            B2[s][nt][1] = packh2(w2[(kb + 8) * 128 + n], w2[(kb + 9) * 128 + n]);
        }
    float w3a[4], w3b[4];
#pragma unroll
    for (int nt = 0; nt < 4; nt++) {
        w3a[nt] = __ldg(w3 + ng * 32 + nt * 8 + 2 * q);
        w3b[nt] = __ldg(w3 + ng * 32 + nt * 8 + 2 * q + 1);
    }

    const uint32_t xfrag_off = (uint32_t)(lrow * XS_STRIDE_H + lcol) * 2;
    const uint32_t h1lda = H1u + (uint32_t)(lrow * H1_STRIDE_H + lcol) * 2;
    const uint32_t h1sta = H1u + (uint32_t)(lrow * H1_STRIDE_H + ng * 32 + lcol) * 2;

    BAR_ALL();                          // wait for producers' X0

    int p = 0;
    for (int b = blockIdx.x; b < NBATCH; b += NCTA) {
        const uint32_t xlda = (p ? Xu1 : Xu0) + xfrag_off;

        // ---------------- GEMM1: H1 = relu(X @ W1), M=64 --------------------
        float acc[4][4][4];
#pragma unroll
        for (int mt = 0; mt < 4; mt++)
#pragma unroll
            for (int nt = 0; nt < 4; nt++) {
                acc[mt][nt][0] = 0.f; acc[mt][nt][1] = 0.f;
                acc[mt][nt][2] = 0.f; acc[mt][nt][3] = 0.f;
            }
#pragma unroll
        for (int s = 0; s < 3; s++) {
            uint32_t a[4][4];
#pragma unroll
            for (int mt = 0; mt < 4; mt++)
                LDSM_X4(a[mt], xlda + (uint32_t)(mt * 16 * XS_STRIDE_H * 2 + s * 32));
#pragma unroll
            for (int mt = 0; mt < 4; mt++)
#pragma unroll
                for (int nt = 0; nt < 4; nt++)
                    mma16(acc[mt][nt], a[mt], B1[s][nt]);
        }

        // relu -> fp16 -> H1 smem via stmatrix
#pragma unroll
        for (int mt = 0; mt < 4; mt++) {
            uint32_t v[4][2];
#pragma unroll
            for (int nt = 0; nt < 4; nt++) {
                v[nt][0] = packh2(fmaxf(acc[mt][nt][0], 0.f), fmaxf(acc[mt][nt][1], 0.f));
                v[nt][1] = packh2(fmaxf(acc[mt][nt][2], 0.f), fmaxf(acc[mt][nt][3], 0.f));
            }
            uint32_t sa = h1sta + (uint32_t)(mt * 16 * H1_STRIDE_H * 2);
            STSM_X4(sa, v[0][0], v[0][1], v[1][0], v[1][1]);
            STSM_X4(sa + 32, v[2][0], v[2][1], v[3][0], v[3][1]);
        }
        BAR_CONS();

        // ---------------- GEMM2: H2 = H1 @ W2 -------------------------------
#pragma unroll
        for (int mt = 0; mt < 4; mt++)
#pragma unroll
            for (int nt = 0; nt < 4; nt++) {
                acc[mt][nt][0] = 0.f; acc[mt][nt][1] = 0.f;
                acc[mt][nt][2] = 0.f; acc[mt][nt][3] = 0.f;
            }
#pragma unroll
        for (int s = 0; s < 8; s++) {
            uint32_t a[4][4];
#pragma unroll
            for (int mt = 0; mt < 4; mt++)
                LDSM_X4(a[mt], h1lda + (uint32_t)(mt * 16 * H1_STRIDE_H * 2 + s * 32));
#pragma unroll
            for (int mt = 0; mt < 4; mt++)
#pragma unroll
                for (int nt = 0; nt < 4; nt++)
                    mma16(acc[mt][nt], a[mt], B2[s][nt]);
        }

        // ---------------- epilogue: partial relu(H2).w3 per N-group ---------
#pragma unroll
        for (int mt = 0; mt < 4; mt++) {
            float s0 = 0.f, s1 = 0.f;
#pragma unroll
            for (int nt = 0; nt < 4; nt++) {
                s0 += fmaxf(acc[mt][nt][0], 0.f) * w3a[nt] + fmaxf(acc[mt][nt][1], 0.f) * w3b[nt];
                s1 += fmaxf(acc[mt][nt][2], 0.f) * w3a[nt] + fmaxf(acc[mt][nt][3], 0.f) * w3b[nt];
            }
            s0 += __shfl_xor_sync(0xffffffffu, s0, 1);
            s0 += __shfl_xor_sync(0xffffffffu, s0, 2);
            s1 += __shfl_xor_sync(0xffffffffu, s1, 1);
            s1 += __shfl_xor_sync(0xffffffffu, s1, 2);
            if (q == 0) {
                int r0 = mt * 16 + ln4;
                part[ng * 64 + r0] = s0;
                part[ng * 64 + r0 + 8] = s1;
            }
        }
        BAR_CONS();

        if (tid < 64) {
            float o = (part[tid] + part[64 + tid] + part[128 + tid] + part[192 + tid]) * INV_SCALE;
            out[b * 64 + tid] = o;
        }

        // joint handshake: our X[p] reads are done; producers' X[1-p] is ready
        BAR_ALL();
        p ^= 1;
    }
}

extern "C" void kernel_launch(void* const* d_in, const int* in_sizes, int n_in,
                              void* d_out, int out_size) {
    const float* table = nullptr;
    const float* w1 = nullptr;
    const float* w2 = nullptr;
    const float* w3 = nullptr;
    for (int i = 0; i < n_in; i++) {
        switch (in_sizes[i]) {
            case 12 * 1048576 * 4: table = (const float*)d_in[i]; break;
            case 48 * 128:         w1 = (const float*)d_in[i]; break;
            case 128 * 128:        w2 = (const float*)d_in[i]; break;
            case 128:              w3 = (const float*)d_in[i]; break;
            default: break;
        }
    }
    if (!table) table = (const float*)d_in[2];
    if (!w1) w1 = (const float*)d_in[3];
    if (!w2) w2 = (const float*)d_in[4];
    if (!w3) w3 = (const float*)d_in[5];

    cudaFuncSetAttribute(inr_kernel, cudaFuncAttributeMaxDynamicSharedMemorySize, SMEM_BYTES);
    inr_kernel<<<NCTA, NTHREADS, SMEM_BYTES>>>((const float4*)table, w1, w2, w3, (float*)d_out);
}

// round 15
// speedup vs baseline: 1.5869x; 1.5869x over previous
#include <cuda_runtime.h>
#include <cuda_fp16.h>
#include <stdint.h>

// ---------------------------------------------------------------------------
// TCNN INR fused: hash-grid encoding + MLP 48->128->128->1, fp16 HMMA path.
// Persistent grid (304 CTAs = 2/SM), 128-thread CTAs (M=64, 4 warps x 32 N).
// Encoding lane map warp-uniform in LEVEL; 3-chunk software pipeline issues
// next batch's gathers under current GEMM2 (double-buffered X tile).
// R15: merged tail barrier (2 barriers/batch) + odd-CTA half-batch phase
// offset so co-resident CTAs overlap encode vs tensor phases.
// Weights persistent in registers. Encodings scaled by 2^14 vs fp16 denorms.
// ---------------------------------------------------------------------------

#define NBATCH 16384           // 1024*1024 / 64 pixels per batch
#define NCTA 304               // 2 per SM, grid-stride over batches
#define SCALE 16384.0f
#define INV_SCALE (1.0f / 16384.0f)

#define XS_STRIDE_H 56         // 48 cols + pad (112B rows, 16B-aligned)
#define H1_STRIDE_H 136        // 128 cols + pad (272B rows, 16B-aligned)
#define SM_X_BYTES (64 * XS_STRIDE_H * 2)     // 7168 (x2 buffers)
#define SM_H1_BYTES (64 * H1_STRIDE_H * 2)    // 17408
#define SM_PART_BYTES (4 * 64 * 4)            // 1024
#define SMEM_BYTES (2 * SM_X_BYTES + SM_H1_BYTES + SM_PART_BYTES)

__constant__ float c_scale[12] = {
    15.0f, 23.0f, 35.0f, 53.0f, 80.0f, 120.5f, 181.25f, 272.375f,
    409.0625f, 614.09375f, 921.640625f, 1382.9609375f};
__constant__ uint32_t c_res[12] = {16, 24, 36, 54, 81, 122, 183, 274, 411, 616, 923, 1384};

static __device__ __forceinline__ uint32_t packh2(float lo, float hi) {
    __half2 h = __floats2half2_rn(lo, hi);
    return *(uint32_t*)&h;
}

static __device__ __forceinline__ void mma16(float d[4], const uint32_t a[4], const uint32_t b[2]) {
    asm volatile(
        "mma.sync.aligned.m16n8k16.row.col.f32.f16.f16.f32 "
        "{%0,%1,%2,%3}, {%4,%5,%6,%7}, {%8,%9}, {%0,%1,%2,%3};"
        : "+f"(d[0]), "+f"(d[1]), "+f"(d[2]), "+f"(d[3])
        : "r"(a[0]), "r"(a[1]), "r"(a[2]), "r"(a[3]), "r"(b[0]), "r"(b[1]));
}

#define LDSM_X4(r, addr) \
    asm volatile("ldmatrix.sync.aligned.m8n8.x4.shared.b16 {%0,%1,%2,%3}, [%4];" \
        : "=r"((r)[0]), "=r"((r)[1]), "=r"((r)[2]), "=r"((r)[3]) : "r"(addr))

#define STSM_X4(addr, r0, r1, r2, r3) \
    asm volatile("stmatrix.sync.aligned.m8n8.x4.shared.b16 [%0], {%1,%2,%3,%4};" \
        :: "r"(addr), "r"(r0), "r"(r1), "r"(r2), "r"(r3) : "memory")

// one 2-level encoding chunk held in registers between gather and interp
struct EncChunk2 {
    float4 t[2][4];
    float wx[2], wy[2];
};

static __device__ __forceinline__ void enc_gather2(
    int lb, float fx, float fy, const float4* __restrict__ tab, EncChunk2& c)
{
#pragma unroll
    for (int j = 0; j < 2; j++) {
        const int l = lb + j;
        const float s = c_scale[l];
        const uint32_t R = c_res[l];
        float px = fx * s + 0.5f, py = fy * s + 0.5f;
        float fpx = floorf(px), fpy = floorf(py);
        c.wx[j] = px - fpx; c.wy[j] = py - fpy;
        uint32_t ux = (uint32_t)fpx, uy = (uint32_t)fpy;
        uint32_t x0 = min(ux, R - 1u), x1 = min(ux + 1u, R - 1u);
        uint32_t y0 = min(uy, R - 1u), y1 = min(uy + 1u, R - 1u);
        uint32_t i00, i10, i01, i11;
        if (l < 11) {
            i00 = x0 + y0 * R; i10 = x1 + y0 * R;
            i01 = x0 + y1 * R; i11 = x1 + y1 * R;
        } else {
            uint32_t h0 = y0 * 2654435761u, h1 = y1 * 2654435761u;
            i00 = (x0 ^ h0) & 0xFFFFFu; i10 = (x1 ^ h0) & 0xFFFFFu;
            i01 = (x0 ^ h1) & 0xFFFFFu; i11 = (x1 ^ h1) & 0xFFFFFu;
        }
        const float4* base = tab + ((size_t)l << 20);
        c.t[j][0] = __ldg(base + i00);
        c.t[j][1] = __ldg(base + i10);
        c.t[j][2] = __ldg(base + i01);
        c.t[j][3] = __ldg(base + i11);
    }
}

static __device__ __forceinline__ void enc_store2(int lb, const EncChunk2& c, uint2* dst)
{
#pragma unroll
    for (int j = 0; j < 2; j++) {
        float wx = c.wx[j], wy = c.wy[j];
        float w00 = (1.f - wx) * (1.f - wy) * SCALE, w10 = wx * (1.f - wy) * SCALE;
        float w01 = (1.f - wx) * wy * SCALE,         w11 = wx * wy * SCALE;
        float e0 = c.t[j][0].x * w00 + c.t[j][1].x * w10 + c.t[j][2].x * w01 + c.t[j][3].x * w11;
        float e1 = c.t[j][0].y * w00 + c.t[j][1].y * w10 + c.t[j][2].y * w01 + c.t[j][3].y * w11;
        float e2 = c.t[j][0].z * w00 + c.t[j][1].z * w10 + c.t[j][2].z * w01 + c.t[j][3].z * w11;
        float e3 = c.t[j][0].w * w00 + c.t[j][1].w * w10 + c.t[j][2].w * w01 + c.t[j][3].w * w11;
        uint2 v;
        v.x = packh2(e0, e1);
        v.y = packh2(e2, e3);
        dst[lb + j] = v;
    }
}

__global__ __launch_bounds__(128, 2) void inr_kernel(
    const float4* __restrict__ tab,   // [12][2^20] float4
    const float* __restrict__ w1,     // [48][128]
    const float* __restrict__ w2,     // [128][128]
    const float* __restrict__ w3,     // [128]
    float* __restrict__ out)          // [1024*1024]
{
    extern __shared__ char smem[];
    __half* X0 = (__half*)smem;                        // [64][56] buffer 0
    __half* X1 = (__half*)(smem + SM_X_BYTES);         // [64][56] buffer 1
    __half* H1h = (__half*)(smem + 2 * SM_X_BYTES);    // [64][136]
    float* part = (float*)(smem + 2 * SM_X_BYTES + SM_H1_BYTES);

    const uint32_t Xu0 = (uint32_t)__cvta_generic_to_shared(X0);
    const uint32_t Xu1 = (uint32_t)__cvta_generic_to_shared(X1);
    const uint32_t H1u = (uint32_t)__cvta_generic_to_shared(H1h);

    const int tid = threadIdx.x;
    const int lane = tid & 31, ng = tid >> 5;   // warp = N-group (32 cols)
    const int q = lane & 3, ln4 = lane >> 2;
    const int lrow = lane & 15;
    const int lcol = (lane >> 4) << 3;

    // ---- persistent B fragments (weights), loaded once per CTA ----
    uint32_t B1[3][4][2];
    uint32_t B2[8][4][2];
#pragma unroll
    for (int s = 0; s < 3; s++)
#pragma unroll
        for (int nt = 0; nt < 4; nt++) {
            int kb = s * 16 + 2 * q;
            int n = ng * 32 + nt * 8 + ln4;
            B1[s][nt][0] = packh2(w1[(kb + 0) * 128 + n], w1[(kb + 1) * 128 + n]);
            B1[s][nt][1] = packh2(w1[(kb + 8) * 128 + n], w1[(kb + 9) * 128 + n]);
        }
#pragma unroll
    for (int s = 0; s < 8; s++)
#pragma unroll
        for (int nt = 0; nt < 4; nt++) {
            int kb = s * 16 + 2 * q;
            int n = ng * 32 + nt * 8 + ln4;
            B2[s][nt][0] = packh2(w2[(kb + 0) * 128 + n], w2[(kb + 1) * 128 + n]);
            B2[s][nt][1] = packh2(w2[(kb + 8) * 128 + n], w2[(kb + 9) * 128 + n]);
        }

    const uint32_t xfrag_off = (uint32_t)(lrow * XS_STRIDE_H + lcol) * 2;
    const uint32_t h1lda = H1u + (uint32_t)(lrow * H1_STRIDE_H + lcol) * 2;
    const uint32_t h1sta = H1u + (uint32_t)(lrow * H1_STRIDE_H + ng * 32 + lcol) * 2;

    // encoding assignment: warp-uniform level, consecutive pixels per warp.
    const int er = ((ng & 1) << 5) | lane;   // pixel row 0..63
    const int el0 = (ng >> 1) * 6;           // this warp's 6-level window

    // ---- prologue: encode first batch into X0 ----
    // odd CTAs run it twice: ~half-batch delay dephases the two co-resident
    // CTAs so encode(LSU) phases overlap the peer's GEMM(tensor) phases.
    const int reps = 1 + (int)(blockIdx.x & 1);
    for (int rep = 0; rep < reps; rep++) {
        const int pix = blockIdx.x * 64 + er;
        const float fx = (float)(pix & 1023) * (1.0f / 1023.0f);
        const float fy = (float)(pix >> 10) * (1.0f / 1023.0f);
        uint2* dst = (uint2*)(X0 + er * XS_STRIDE_H);
        EncChunk2 c;
#pragma unroll
        for (int k = 0; k < 3; k++) {
            enc_gather2(el0 + 2 * k, fx, fy, tab, c);
            enc_store2(el0 + 2 * k, c, dst);
        }
        __syncthreads();
    }

    int p = 0;
    for (int b = blockIdx.x; b < NBATCH; b += NCTA) {
        const uint32_t xlda = (p ? Xu1 : Xu0) + xfrag_off;
        uint2* xdstn = (uint2*)((p ? X0 : X1) + er * XS_STRIDE_H);  // next buffer
        // next batch coords (out-of-range prefetch on last iter is clamped/safe)
        const int pnx = (b + NCTA) * 64 + er;
        const float nfx = (float)(pnx & 1023) * (1.0f / 1023.0f);
        const float nfy = (float)(pnx >> 10) * (1.0f / 1023.0f);

        // ---------------- GEMM1: H1 = relu(X @ W1), M=64 --------------------
        float acc[4][4][4];
#pragma unroll
        for (int mt = 0; mt < 4; mt++)
#pragma unroll
            for (int nt = 0; nt < 4; nt++) {
                acc[mt][nt][0] = 0.f; acc[mt][nt][1] = 0.f;
                acc[mt][nt][2] = 0.f; acc[mt][nt][3] = 0.f;
            }
#pragma unroll
        for (int s = 0; s < 3; s++) {
            uint32_t a[4][4];
#pragma unroll
            for (int mt = 0; mt < 4; mt++)
                LDSM_X4(a[mt], xlda + (uint32_t)(mt * 16 * XS_STRIDE_H * 2 + s * 32));
#pragma unroll
            for (int mt = 0; mt < 4; mt++)
#pragma unroll
                for (int nt = 0; nt < 4; nt++)
                    mma16(acc[mt][nt], a[mt], B1[s][nt]);
        }

        // prefetch chunk0 of next batch (hides under STSM + sync + GEMM2 s0-2)
        EncChunk2 ec;
        enc_gather2(el0, nfx, nfy, tab, ec);

        // relu -> fp16 -> H1 smem via stmatrix
#pragma unroll
        for (int mt = 0; mt < 4; mt++) {
            uint32_t v[4][2];
#pragma unroll
            for (int nt = 0; nt < 4; nt++) {
                v[nt][0] = packh2(fmaxf(acc[mt][nt][0], 0.f), fmaxf(acc[mt][nt][1], 0.f));
                v[nt][1] = packh2(fmaxf(acc[mt][nt][2], 0.f), fmaxf(acc[mt][nt][3], 0.f));
            }
            uint32_t sa = h1sta + (uint32_t)(mt * 16 * H1_STRIDE_H * 2);
            STSM_X4(sa, v[0][0], v[0][1], v[1][0], v[1][1]);
            STSM_X4(sa + 32, v[2][0], v[2][1], v[3][0], v[3][1]);
        }
        __syncthreads();   // H1 published (also closes X[p] reads)

        // ---------------- GEMM2: s = 0..2 -----------------------------------
#pragma unroll
        for (int mt = 0; mt < 4; mt++)
#pragma unroll
            for (int nt = 0; nt < 4; nt++) {
                acc[mt][nt][0] = 0.f; acc[mt][nt][1] = 0.f;
                acc[mt][nt][2] = 0.f; acc[mt][nt][3] = 0.f;
            }
#pragma unroll
        for (int s = 0; s < 3; s++) {
            uint32_t a[4][4];
#pragma unroll
            for (int mt = 0; mt < 4; mt++)
                LDSM_X4(a[mt], h1lda + (uint32_t)(mt * 16 * H1_STRIDE_H * 2 + s * 32));
#pragma unroll
            for (int mt = 0; mt < 4; mt++)
#pragma unroll
                for (int nt = 0; nt < 4; nt++)
                    mma16(acc[mt][nt], a[mt], B2[s][nt]);
        }

        // chunk0 -> next X buffer; issue chunk1 gathers
        enc_store2(el0, ec, xdstn);
        enc_gather2(el0 + 2, nfx, nfy, tab, ec);

        // ---------------- GEMM2: s = 3..5 -----------------------------------
#pragma unroll
        for (int s = 3; s < 6; s++) {
            uint32_t a[4][4];
#pragma unroll
            for (int mt = 0; mt < 4; mt++)
                LDSM_X4(a[mt], h1lda + (uint32_t)(mt * 16 * H1_STRIDE_H * 2 + s * 32));
#pragma unroll
            for (int mt = 0; mt < 4; mt++)
#pragma unroll
                for (int nt = 0; nt < 4; nt++)
                    mma16(acc[mt][nt], a[mt], B2[s][nt]);
        }

        // chunk1 -> next X buffer; issue chunk2 gathers
        enc_store2(el0 + 2, ec, xdstn);
        enc_gather2(el0 + 4, nfx, nfy, tab, ec);

        // ---------------- GEMM2: s = 6..7 -----------------------------------
#pragma unroll
        for (int s = 6; s < 8; s++) {
            uint32_t a[4][4];
#pragma unroll
            for (int mt = 0; mt < 4; mt++)
                LDSM_X4(a[mt], h1lda + (uint32_t)(mt * 16 * H1_STRIDE_H * 2 + s * 32));
#pragma unroll
            for (int mt = 0; mt < 4; mt++)
#pragma unroll
                for (int nt = 0; nt < 4; nt++)
                    mma16(acc[mt][nt], a[mt], B2[s][nt]);
        }

        // ---------------- epilogue: partial relu(H2).w3 per N-group ---------
        {
            float w3a[4], w3b[4];
#pragma unroll
            for (int nt = 0; nt < 4; nt++) {
                w3a[nt] = __ldg(w3 + ng * 32 + nt * 8 + 2 * q);
                w3b[nt] = __ldg(w3 + ng * 32 + nt * 8 + 2 * q + 1);
            }
#pragma unroll
            for (int mt = 0; mt < 4; mt++) {
                float s0 = 0.f, s1 = 0.f;
#pragma unroll
                for (int nt = 0; nt < 4; nt++) {
                    s0 += fmaxf(acc[mt][nt][0], 0.f) * w3a[nt] + fmaxf(acc[mt][nt][1], 0.f) * w3b[nt];
                    s1 += fmaxf(acc[mt][nt][2], 0.f) * w3a[nt] + fmaxf(acc[mt][nt][3], 0.f) * w3b[nt];
                }
                s0 += __shfl_xor_sync(0xffffffffu, s0, 1);
                s0 += __shfl_xor_sync(0xffffffffu, s0, 2);
                s1 += __shfl_xor_sync(0xffffffffu, s1, 1);
                s1 += __shfl_xor_sync(0xffffffffu, s1, 2);
                if (q == 0) {
                    int r0 = mt * 16 + ln4;
                    part[ng * 64 + r0] = s0;
                    part[ng * 64 + r0 + 8] = s1;
                }
            }
        }

        // chunk2 -> next X buffer, then ONE barrier publishes part AND X
        enc_store2(el0 + 4, ec, xdstn);
        __syncthreads();

        if (tid < 64) {
            float o = (part[tid] + part[64 + tid] + part[128 + tid] + part[192 + tid]) * INV_SCALE;
            out[b * 64 + tid] = o;
        }
        // part reads (above) are ordered vs next iteration's part writes by
        // the next post-STSM __syncthreads; X[new p] was published here.
        p ^= 1;
    }
}

extern "C" void kernel_launch(void* const* d_in, const int* in_sizes, int n_in,
                              void* d_out, int out_size) {
    const float* table = nullptr;
    const float* w1 = nullptr;
    const float* w2 = nullptr;
    const float* w3 = nullptr;
    for (int i = 0; i < n_in; i++) {
        switch (in_sizes[i]) {
            case 12 * 1048576 * 4: table = (const float*)d_in[i]; break;
            case 48 * 128:         w1 = (const float*)d_in[i]; break;
            case 128 * 128:        w2 = (const float*)d_in[i]; break;
            case 128:              w3 = (const float*)d_in[i]; break;
            default: break;
        }
    }
    if (!table) table = (const float*)d_in[2];
    if (!w1) w1 = (const float*)d_in[3];
    if (!w2) w2 = (const float*)d_in[4];
    if (!w3) w3 = (const float*)d_in[5];

    cudaFuncSetAttribute(inr_kernel, cudaFuncAttributeMaxDynamicSharedMemorySize, SMEM_BYTES);
    inr_kernel<<<NCTA, 128, SMEM_BYTES>>>((const float4*)table, w1, w2, w3, (float*)d_out);
}